// round 4
// baseline (speedup 1.0000x reference)
#include <cuda_runtime.h>
#include <cuda_bf16.h>
#include <cstdint>

#define S_LEN 2048
#define HID   512
#define IN_D  128
#define OUT_D 64
#define ALPHA 0.2f
#define CLU   8          // CTAs per cluster = hidden-column splits
#define NGRP  16         // batch groups (clusters)

typedef unsigned long long ull;

// ---- dynamic smem layout (float offsets) ----
#define MB_OFF   0                     // mbarrier (8B) + 8 remote-mbar addrs (u32) at [2..9]
#define H_OFF    12                    // h[2][4][520]
#define H_ROW    520
#define H_BUF    (4 * H_ROW)           // 2080
#define X_OFF    (H_OFF + 2 * H_BUF)   // 4172 : x[2][512]
#define RED_OFF  (X_OFF + 2 * 512)     // 5196 : red[16][260]
#define RED_ROW  260
#define WHO_OFF  (RED_OFF + 16 * RED_ROW) // 9356 : who[8][520]
#define WHO_ROW  520
#define SMEM_FLOATS (WHO_OFF + 8 * WHO_ROW) // 13516
#define SMEM_BYTES  (SMEM_FLOATS * 4)       // 54064

// ---------------- packed f32x2 helpers ----------------
__device__ __forceinline__ ull fma2(ull a, ull b, ull c) {
    ull d;
    asm("fma.rn.f32x2 %0, %1, %2, %3;" : "=l"(d) : "l"(a), "l"(b), "l"(c));
    return d;
}
__device__ __forceinline__ ull pack2(float a, float b) {
    ull r;
    asm("mov.b64 %0, {%1, %2};" : "=l"(r) : "r"(__float_as_uint(a)), "r"(__float_as_uint(b)));
    return r;
}
__device__ __forceinline__ float lo2(ull v) { return __uint_as_float((unsigned)(v & 0xffffffffull)); }
__device__ __forceinline__ float hi2(ull v) { return __uint_as_float((unsigned)(v >> 32)); }
__device__ __forceinline__ float my_tanh(float v) {
    float e = __expf(2.0f * v);
    return 1.0f - 2.0f / (e + 1.0f);
}
__device__ __forceinline__ uint32_t smem_u32(const void* p) {
    uint32_t a;
    asm("{ .reg .u64 t; cvta.to.shared.u64 t, %1; cvt.u32.u64 %0, t; }" : "=r"(a) : "l"(p));
    return a;
}
__device__ __forceinline__ void mbar_wait_cluster(uint32_t mbar, uint32_t parity) {
    uint32_t done;
    asm volatile(
        "{\n\t.reg .pred p;\n\t"
        "mbarrier.try_wait.parity.acquire.cluster.shared::cta.b64 p, [%1], %2, 0x989680;\n\t"
        "selp.b32 %0, 1, 0, p;\n\t}"
        : "=r"(done) : "r"(mbar), "r"(parity) : "memory");
    while (!done) {
        asm volatile(
            "{\n\t.reg .pred p;\n\t"
            "mbarrier.try_wait.parity.acquire.cluster.shared::cta.b64 p, [%1], %2, 0x989680;\n\t"
            "selp.b32 %0, 1, 0, p;\n\t}"
            : "=r"(done) : "r"(mbar), "r"(parity) : "memory");
    }
}

// warp-tiled readout: out[b0..b0+1][srow][o0..o0+1] from full h buffer in smem
__device__ __forceinline__ void do_readout(const float* hbuf, const float* who,
                                           int warp, int lane, int g, int cs,
                                           int srow, float* out) {
    const int b0 = (warp >> 2) * 2;
    const int o0 = (warp & 3) * 2;
    const ulonglong2* h0p = (const ulonglong2*)(hbuf + b0 * H_ROW + lane * 16);
    const ulonglong2* h1p = (const ulonglong2*)(hbuf + (b0 + 1) * H_ROW + lane * 16);
    const ulonglong2* w0p = (const ulonglong2*)(who + o0 * WHO_ROW + lane * 16);
    const ulonglong2* w1p = (const ulonglong2*)(who + (o0 + 1) * WHO_ROW + lane * 16);
    ull a00 = 0, a01 = 0, a10 = 0, a11 = 0;
#pragma unroll
    for (int c = 0; c < 4; c++) {
        ulonglong2 h0 = h0p[c], h1 = h1p[c], w0 = w0p[c], w1 = w1p[c];
        a00 = fma2(h0.x, w0.x, a00); a00 = fma2(h0.y, w0.y, a00);
        a01 = fma2(h0.x, w1.x, a01); a01 = fma2(h0.y, w1.y, a01);
        a10 = fma2(h1.x, w0.x, a10); a10 = fma2(h1.y, w0.y, a10);
        a11 = fma2(h1.x, w1.x, a11); a11 = fma2(h1.y, w1.y, a11);
    }
    float f00 = lo2(a00) + hi2(a00), f01 = lo2(a01) + hi2(a01);
    float f10 = lo2(a10) + hi2(a10), f11 = lo2(a11) + hi2(a11);
#pragma unroll
    for (int off = 16; off; off >>= 1) {
        f00 += __shfl_xor_sync(~0u, f00, off);
        f01 += __shfl_xor_sync(~0u, f01, off);
        f10 += __shfl_xor_sync(~0u, f10, off);
        f11 += __shfl_xor_sync(~0u, f11, off);
    }
    if (lane == 0) {
        size_t base = ((size_t)(g * 4 + b0) * S_LEN + srow) * OUT_D + cs * 8 + o0;
        size_t rstride = (size_t)S_LEN * OUT_D;
        out[base] = f00;           out[base + 1] = f01;
        out[base + rstride] = f10; out[base + rstride + 1] = f11;
    }
}

__global__ void __launch_bounds__(256, 1) __cluster_dims__(CLU, 1, 1)
rnn_cluster_kernel(const float* __restrict__ x,     // [64][2048][128]
                   const float* __restrict__ Wih,   // [128][512]
                   const float* __restrict__ Wrec,  // [512][512]
                   const float* __restrict__ Who,   // [512][64]
                   float* __restrict__ out)         // [64][2048][64]
{
    extern __shared__ float smem[];
    float* h_s   = smem + H_OFF;
    float* x_s   = smem + X_OFF;
    float* red   = smem + RED_OFF;
    float* who_s = smem + WHO_OFF;

    const uint32_t sbase = smem_u32(smem);
    const int t    = threadIdx.x;
    const int warp = t >> 5, lane = t & 31;
    const int g    = blockIdx.x >> 3;      // batch group (cluster id)
    const int cs   = blockIdx.x & 7;       // cluster rank = column split

    // compute-thread mapping
    const int nj = t & 15;                 // 4 cols each
    const int ks = t >> 4;                 // 16 k-splits of 32 k
    const int n0 = cs * 64 + nj * 4;
    const int k0 = ks * 32;
    const int i0 = ks * 8;
    const int b_loc = t >> 6, nl = t & 63; // finalize mapping

    // ---- mbarrier init + remote base translation ----
    if (t == 0) {
        asm volatile("mbarrier.init.shared.b64 [%0], %1;" :: "r"(sbase), "r"(CLU) : "memory");
    }
    uint32_t mapa_base[CLU];
#pragma unroll
    for (int r = 0; r < CLU; r++)
        asm("mapa.shared::cluster.u32 %0, %1, %2;" : "=r"(mapa_base[r]) : "r"(sbase), "r"(r));
    if (t < CLU) ((uint32_t*)smem)[2 + t] = mapa_base[t];  // remote mbar addrs (offset 0)

    // ---- W_rec slice -> registers (k-pair packed) ----
    ull wr[64];
#pragma unroll
    for (int kp = 0; kp < 16; kp++) {
        float4 we = *(const float4*)&Wrec[(k0 + 2 * kp)     * HID + n0];
        float4 wo = *(const float4*)&Wrec[(k0 + 2 * kp + 1) * HID + n0];
        wr[kp * 4 + 0] = pack2(we.x, wo.x);
        wr[kp * 4 + 1] = pack2(we.y, wo.y);
        wr[kp * 4 + 2] = pack2(we.z, wo.z);
        wr[kp * 4 + 3] = pack2(we.w, wo.w);
    }
    ull wi[16];
#pragma unroll
    for (int ip = 0; ip < 4; ip++) {
        float4 we = *(const float4*)&Wih[(i0 + 2 * ip)     * HID + n0];
        float4 wo = *(const float4*)&Wih[(i0 + 2 * ip + 1) * HID + n0];
        wi[ip * 4 + 0] = pack2(we.x, wo.x);
        wi[ip * 4 + 1] = pack2(we.y, wo.y);
        wi[ip * 4 + 2] = pack2(we.z, wo.z);
        wi[ip * 4 + 3] = pack2(we.w, wo.w);
    }
    // Who o-slice transposed [o][k]
    for (int idx = t; idx < 8 * 512; idx += 256) {
        int ol = idx >> 9, k = idx & 511;
        who_s[ol * WHO_ROW + k] = Who[k * OUT_D + cs * 8 + ol];
    }
    // h0 = 0 (buffer 0), stage x[s=0]
    for (int idx = t; idx < H_BUF; idx += 256) h_s[idx] = 0.0f;
    const int bb = t >> 6;
    const int i2 = (t & 63) * 2;
    *(float2*)&x_s[bb * 128 + i2] =
        *(const float2*)&x[((size_t)(g * 4 + bb) * S_LEN) * IN_D + i2];

    __syncthreads();
    asm volatile("barrier.cluster.arrive.aligned;" ::: "memory");
    asm volatile("barrier.cluster.wait.aligned;"   ::: "memory");

#pragma unroll 1
    for (int s = 0; s < S_LEN; s++) {
        const int ph = s & 1, pn = ph ^ 1;
        const float* hb = h_s + ph * H_BUF;

        // prefetch next x tile
        float2 xn = make_float2(0.0f, 0.0f);
        if (s + 1 < S_LEN)
            xn = *(const float2*)&x[((size_t)(g * 4 + bb) * S_LEN + (s + 1)) * IN_D + i2];

        // ---- h@Wrec + x@Wih partials ----
        ull acc[16];
#pragma unroll
        for (int q = 0; q < 16; q++) acc[q] = 0ull;
#pragma unroll
        for (int c = 0; c < 8; c++) {
            int kk = k0 + c * 4;
#pragma unroll
            for (int b = 0; b < 4; b++) {
                ulonglong2 h2 = *(const ulonglong2*)&hb[b * H_ROW + kk];
#pragma unroll
                for (int j = 0; j < 4; j++) {
                    acc[b * 4 + j] = fma2(h2.x, wr[(c * 2) * 4 + j],     acc[b * 4 + j]);
                    acc[b * 4 + j] = fma2(h2.y, wr[(c * 2 + 1) * 4 + j], acc[b * 4 + j]);
                }
            }
        }
        const float* xb = x_s + ph * 512;
#pragma unroll
        for (int c = 0; c < 2; c++) {
            int ii = i0 + c * 4;
#pragma unroll
            for (int b = 0; b < 4; b++) {
                ulonglong2 x2 = *(const ulonglong2*)&xb[b * 128 + ii];
#pragma unroll
                for (int j = 0; j < 4; j++) {
                    acc[b * 4 + j] = fma2(x2.x, wi[(c * 2) * 4 + j],     acc[b * 4 + j]);
                    acc[b * 4 + j] = fma2(x2.y, wi[(c * 2 + 1) * 4 + j], acc[b * 4 + j]);
                }
            }
        }
        // stage prefetched x
        *(float2*)&x_s[pn * 512 + bb * 128 + i2] = xn;

        // partials -> smem
#pragma unroll
        for (int b = 0; b < 4; b++) {
            float4 v;
            v.x = lo2(acc[b * 4 + 0]) + hi2(acc[b * 4 + 0]);
            v.y = lo2(acc[b * 4 + 1]) + hi2(acc[b * 4 + 1]);
            v.z = lo2(acc[b * 4 + 2]) + hi2(acc[b * 4 + 2]);
            v.w = lo2(acc[b * 4 + 3]) + hi2(acc[b * 4 + 3]);
            *(float4*)&red[ks * RED_ROW + b * 64 + nj * 4] = v;
        }

        // readout for previous step (reads same live buffer, off critical path)
        if (s) do_readout(hb, who_s, warp, lane, g, cs, s - 1, out);

        __syncthreads();                                   // S1

        // reduce 16 k-splits
        float pre = 0.0f;
#pragma unroll
        for (int r = 0; r < 16; r++) pre += red[r * RED_ROW + t];

        // activation + leaky update
        float hold = hb[b_loc * H_ROW + cs * 64 + nl];
        float hnew = (1.0f - ALPHA) * hold + ALPHA * my_tanh(pre);

        // DSMEM broadcast of own h value into all 8 CTAs' next buffer
        uint32_t off = (uint32_t)((H_OFF + pn * H_BUF + b_loc * H_ROW + cs * 64 + nl) * 4);
#pragma unroll
        for (int r = 0; r < CLU; r++)
            asm volatile("st.shared::cluster.f32 [%0], %1;"
                         :: "r"(mapa_base[r] + off), "f"(hnew) : "memory");

        __syncthreads();                                   // S2 (all stores issued)

        if (t < CLU) {
            uint32_t mb = ((const uint32_t*)smem)[2 + t];
            asm volatile("fence.acq_rel.cluster;" ::: "memory");
            asm volatile("mbarrier.arrive.shared::cluster.b64 _, [%0];" :: "r"(mb) : "memory");
        }
        mbar_wait_cluster(sbase, (uint32_t)(s & 1));
    }

    // final readout: out[.., 2047, ..] from h_2048 (buffer 0)
    do_readout(h_s, who_s, warp, lane, g, cs, S_LEN - 1, out);
}

extern "C" void kernel_launch(void* const* d_in, const int* in_sizes, int n_in,
                              void* d_out, int out_size) {
    const float* x    = (const float*)d_in[0];
    const float* Wih  = (const float*)d_in[1];
    const float* Wrec = (const float*)d_in[2];
    const float* Who  = (const float*)d_in[3];
    float* out = (float*)d_out;

    cudaFuncSetAttribute(rnn_cluster_kernel,
                         cudaFuncAttributeMaxDynamicSharedMemorySize, SMEM_BYTES);
    rnn_cluster_kernel<<<NGRP * CLU, 256, SMEM_BYTES>>>(x, Wih, Wrec, Who, out);
}